// round 1
// baseline (speedup 1.0000x reference)
#include <cuda_runtime.h>
#include <cstdint>

// Problem constants (fixed shapes)
#define B_    240
#define S_    64
#define H_    768
#define NH_   12
#define HD_   64
#define L0_   384
#define L1_   128
#define LT_   576          // L0+L1+S
#define BS_   8            // cache0 batch = B / slot_dim = 240/30
#define ROWS_ (B_*S_)      // 15360
#define OUTSZ (B_*S_*H_)   // 11796480

// scratch for q in [B, nh, S, hd] layout
__device__ float g_q[B_ * NH_ * S_ * HD_];

// ---------------------------------------------------------------------------
// Kernel 1: QKV projection.  C = hidden @ W^T + b
// hidden: [15360, 768] row-major, W: [768, 768] row-major (c,k) -> NT GEMM.
// Output written in [B, nh, S, hd] layout (heads-transposed).
// grid = (12 n-tiles, 240 m-tiles, 3 matrices), block = 256
// ---------------------------------------------------------------------------
__global__ __launch_bounds__(256) void qkv_kernel(
    const float* __restrict__ hidden,
    const float* __restrict__ Wq, const float* __restrict__ bq,
    const float* __restrict__ Wk, const float* __restrict__ bk,
    const float* __restrict__ Wv, const float* __restrict__ bv,
    float* __restrict__ kout, float* __restrict__ vout)
{
    const int bx = blockIdx.x;   // n tile (head)
    const int by = blockIdx.y;   // m tile (batch, since BM=64=S)
    const int sel = blockIdx.z;  // 0=q 1=k 2=v

    const float* W    = (sel == 0) ? Wq : (sel == 1) ? Wk : Wv;
    const float* bias = (sel == 0) ? bq : (sel == 1) ? bk : bv;
    float* dst        = (sel == 0) ? g_q : (sel == 1) ? kout : vout;

    __shared__ float As[16][64];  // [kk][m]
    __shared__ float Bs[16][64];  // [kk][n]

    const int tid = threadIdx.x;
    const int ty = tid >> 4;      // 0..15 (m group)
    const int tx = tid & 15;      // 0..15 (n group)

    const int lr = tid >> 2;          // 0..63 row within tile for loads
    const int lk = (tid & 3) * 4;     // k offset within BK for loads

    float acc[4][4];
#pragma unroll
    for (int i = 0; i < 4; i++)
#pragma unroll
        for (int j = 0; j < 4; j++) acc[i][j] = 0.f;

    const float* Aptr = hidden + (size_t)(by * 64 + lr) * H_;
    const float* Bptr = W      + (size_t)(bx * 64 + lr) * H_;

    for (int k0 = 0; k0 < H_; k0 += 16) {
        float4 a4 = *(const float4*)(Aptr + k0 + lk);
        float4 b4 = *(const float4*)(Bptr + k0 + lk);
        __syncthreads();
        As[lk + 0][lr] = a4.x; As[lk + 1][lr] = a4.y;
        As[lk + 2][lr] = a4.z; As[lk + 3][lr] = a4.w;
        Bs[lk + 0][lr] = b4.x; Bs[lk + 1][lr] = b4.y;
        Bs[lk + 2][lr] = b4.z; Bs[lk + 3][lr] = b4.w;
        __syncthreads();
#pragma unroll
        for (int kk = 0; kk < 16; kk++) {
            float4 av = *(const float4*)&As[kk][ty * 4];
            float4 bv4 = *(const float4*)&Bs[kk][tx * 4];
            float a[4] = {av.x, av.y, av.z, av.w};
            float b[4] = {bv4.x, bv4.y, bv4.z, bv4.w};
#pragma unroll
            for (int i = 0; i < 4; i++)
#pragma unroll
                for (int j = 0; j < 4; j++) acc[i][j] += a[i] * b[j];
        }
    }

    // bias + write in [B, nh, S, hd] layout: b=by, h=bx, s=ty*4+i, d=tx*4+j
    float4 bb = *(const float4*)(bias + bx * 64 + tx * 4);
#pragma unroll
    for (int i = 0; i < 4; i++) {
        int s = ty * 4 + i;
        float4 w;
        w.x = acc[i][0] + bb.x;
        w.y = acc[i][1] + bb.y;
        w.z = acc[i][2] + bb.z;
        w.w = acc[i][3] + bb.w;
        *(float4*)(dst + ((((size_t)by * NH_ + bx) * S_ + s) * HD_ + tx * 4)) = w;
    }
}

// ---------------------------------------------------------------------------
// Kernel 2: attention with two caches, online softmax.
// One block per (b, h). 128 threads = 64 query rows x 2 d-halves (32 each).
// Streams 32-key tiles of K and V through shared memory.
// ---------------------------------------------------------------------------
__global__ __launch_bounds__(128, 4) void attn_kernel(
    const float* __restrict__ kout, const float* __restrict__ vout,
    const float* __restrict__ c0k,  const float* __restrict__ c0v,
    const float* __restrict__ c1k,  const float* __restrict__ c1v,
    const float* __restrict__ mask, float* __restrict__ out)
{
    const int bh = blockIdx.x;
    const int b = bh / NH_;
    const int h = bh % NH_;
    const int tid  = threadIdx.x;
    const int row  = tid >> 1;
    const int half = tid & 1;
    const int doff = half * 32;

    __shared__ float ksm[32][64];
    __shared__ float vsm[32][64];
    __shared__ float msm[32];

    // q row, pre-scaled by 1/sqrt(64)
    float q[32];
    {
        const float* qp = g_q + ((((size_t)b * NH_ + h) * S_ + row) * HD_ + doff);
#pragma unroll
        for (int i = 0; i < 8; i++) {
            float4 v4 = *(const float4*)(qp + 4 * i);
            q[4*i+0] = v4.x * 0.125f; q[4*i+1] = v4.y * 0.125f;
            q[4*i+2] = v4.z * 0.125f; q[4*i+3] = v4.w * 0.125f;
        }
    }

    float o[32];
#pragma unroll
    for (int i = 0; i < 32; i++) o[i] = 0.f;
    float mrun = -1e30f, lrun = 0.f;

    const float* maskb = mask + (size_t)b * LT_;

    for (int seg = 0; seg < 3; seg++) {
        const float *kb, *vb;
        int len, posbase;
        if (seg == 0) {
            size_t off = ((size_t)(b % BS_) * NH_ + h) * L0_ * HD_;
            kb = c0k + off; vb = c0v + off; len = L0_; posbase = 0;
        } else if (seg == 1) {
            size_t off = ((size_t)b * NH_ + h) * L1_ * HD_;
            kb = c1k + off; vb = c1v + off; len = L1_; posbase = L0_;
        } else {
            size_t off = ((size_t)b * NH_ + h) * S_ * HD_;
            kb = kout + off; vb = vout + off; len = S_; posbase = L0_ + L1_;
        }

        for (int t = 0; t < len; t += 32) {
            __syncthreads();
            {
                const float4* ks = (const float4*)(kb + (size_t)t * HD_);
                const float4* vs = (const float4*)(vb + (size_t)t * HD_);
                float4* kd = (float4*)&ksm[0][0];
                float4* vd = (float4*)&vsm[0][0];
#pragma unroll
                for (int u = 0; u < 4; u++) {
                    kd[tid + 128 * u] = ks[tid + 128 * u];
                    vd[tid + 128 * u] = vs[tid + 128 * u];
                }
                if (tid < 32) msm[tid] = maskb[posbase + t + tid];
            }
            __syncthreads();

            // partial scores over this thread's 32 d's, all 32 keys
            float s[32];
#pragma unroll
            for (int j = 0; j < 32; j++) {
                const float4* kr = (const float4*)&ksm[j][doff];
                float a = 0.f;
#pragma unroll
                for (int ii = 0; ii < 8; ii++) {
                    float4 kv = kr[ii];
                    a += q[4*ii+0]*kv.x + q[4*ii+1]*kv.y
                       + q[4*ii+2]*kv.z + q[4*ii+3]*kv.w;
                }
                s[j] = a;
            }
            // combine halves + mask
            float tmax = mrun;
#pragma unroll
            for (int j = 0; j < 32; j++) {
                s[j] += __shfl_xor_sync(0xffffffffu, s[j], 1);
                s[j] += msm[j];
                tmax = fmaxf(tmax, s[j]);
            }
            float corr = __expf(mrun - tmax);
            mrun = tmax;
            lrun *= corr;
#pragma unroll
            for (int i = 0; i < 32; i++) o[i] *= corr;
            float psum = 0.f;
#pragma unroll
            for (int j = 0; j < 32; j++) {
                s[j] = __expf(s[j] - mrun);
                psum += s[j];
            }
            lrun += psum;
            // ctx accumulate
#pragma unroll
            for (int j = 0; j < 32; j++) {
                const float4* vr = (const float4*)&vsm[j][doff];
                float p = s[j];
#pragma unroll
                for (int ii = 0; ii < 8; ii++) {
                    float4 vv = vr[ii];
                    o[4*ii+0] += p * vv.x; o[4*ii+1] += p * vv.y;
                    o[4*ii+2] += p * vv.z; o[4*ii+3] += p * vv.w;
                }
            }
        }
    }

    float inv = 1.f / lrun;
    // out layout [B, S, H]: element (b, s=row, h*64 + d)
    float* op = out + (((size_t)b * S_ + row) * H_ + h * HD_ + doff);
#pragma unroll
    for (int ii = 0; ii < 8; ii++) {
        float4 w;
        w.x = o[4*ii+0] * inv; w.y = o[4*ii+1] * inv;
        w.z = o[4*ii+2] * inv; w.w = o[4*ii+3] * inv;
        ((float4*)op)[ii] = w;
    }
}

// ---------------------------------------------------------------------------
extern "C" void kernel_launch(void* const* d_in, const int* in_sizes, int n_in,
                              void* d_out, int out_size)
{
    const float* hidden = (const float*)d_in[0];
    const float* mask   = (const float*)d_in[1];
    const float* Wq     = (const float*)d_in[2];
    const float* bq     = (const float*)d_in[3];
    const float* Wk     = (const float*)d_in[4];
    const float* bk     = (const float*)d_in[5];
    const float* Wv     = (const float*)d_in[6];
    const float* bv     = (const float*)d_in[7];
    const float* c0k    = (const float*)d_in[8];
    const float* c0v    = (const float*)d_in[9];
    const float* c1k    = (const float*)d_in[10];
    const float* c1v    = (const float*)d_in[11];

    float* out  = (float*)d_out;
    float* kout = out + (size_t)OUTSZ;
    float* vout = out + (size_t)2 * OUTSZ;

    dim3 g1(NH_, B_, 3);
    qkv_kernel<<<g1, 256>>>(hidden, Wq, bq, Wk, bk, Wv, bv, kout, vout);

    attn_kernel<<<B_ * NH_, 128>>>(kout, vout, c0k, c0v, c1k, c1v, mask, out);
}

// round 3
// speedup vs baseline: 3.8582x; 3.8582x over previous
#include <cuda_runtime.h>
#include <cstdint>

// Problem constants (fixed shapes)
#define B_    240
#define S_    64
#define H_    768
#define NH_   12
#define HD_   64
#define L0_   384
#define L1_   128
#define LT_   576          // L0+L1+S
#define BS_   8            // cache0 batch = 240/30
#define OUTSZ (B_*S_*H_)   // 11796480

// scratch for q in [B, nh, S, hd] layout (fp32)
__device__ float g_q[B_ * NH_ * S_ * HD_];

// ---------------------------------------------------------------------------
// tf32 helpers (portable mma.sync path — valid on compute_103 base target)
// ---------------------------------------------------------------------------
__device__ __forceinline__ uint32_t f2tf(float f) {
    uint32_t r;
    asm("cvt.rna.tf32.f32 %0, %1;" : "=r"(r) : "f"(f));
    return r;
}

// D(16x8,f32) += A(16x8,tf32) * B(8x8,tf32)
__device__ __forceinline__ void mma8(float* d, const uint32_t* a, const uint32_t* b) {
    asm volatile(
        "mma.sync.aligned.m16n8k8.row.col.f32.tf32.tf32.f32 "
        "{%0,%1,%2,%3}, {%4,%5,%6,%7}, {%8,%9}, {%0,%1,%2,%3};"
        : "+f"(d[0]), "+f"(d[1]), "+f"(d[2]), "+f"(d[3])
        : "r"(a[0]), "r"(a[1]), "r"(a[2]), "r"(a[3]), "r"(b[0]), "r"(b[1]));
}

// ===========================================================================
// Kernel 1: QKV projection.  C[15360,768] = hidden @ W^T + bias,
// written in [B, nh, S, hd] layout. tf32 mma.sync, 128x128 CTA tile, BK=32.
// grid = (6 n-tiles, 120 m-tiles, 3 matrices), 256 threads (8 warps, 64x32).
// ===========================================================================
#define QPAD 40   // 32 + 8 pad: stride ≡ 8 (mod 32) → conflict-free frag LDS

__global__ __launch_bounds__(256) void qkv_mma_kernel(
    const float* __restrict__ hidden,
    const float* __restrict__ Wq, const float* __restrict__ bq,
    const float* __restrict__ Wk, const float* __restrict__ bk,
    const float* __restrict__ Wv, const float* __restrict__ bv,
    float* __restrict__ kout, float* __restrict__ vout)
{
    __shared__ uint32_t As[128 * QPAD];
    __shared__ uint32_t Bs[128 * QPAD];

    const int tid = threadIdx.x, lane = tid & 31, warp = tid >> 5;
    const int gid = lane >> 2, tig = lane & 3;
    const int nt = blockIdx.x, mt = blockIdx.y, sel = blockIdx.z;

    const float* W    = (sel == 0) ? Wq : (sel == 1) ? Wk : Wv;
    const float* bias = (sel == 0) ? bq : (sel == 1) ? bk : bv;
    float* dst        = (sel == 0) ? g_q : (sel == 1) ? kout : vout;

    const int m0 = mt * 128, n0 = nt * 128;
    const int wm = (warp >> 2) * 64, wn = (warp & 3) * 32;

    float acc[4][4][4];
#pragma unroll
    for (int mi = 0; mi < 4; mi++)
#pragma unroll
        for (int ni = 0; ni < 4; ni++)
#pragma unroll
            for (int j = 0; j < 4; j++) acc[mi][ni][j] = 0.f;

    const int lr = tid >> 3;           // 0..31
    const int lc = (tid & 7) * 4;      // 0..28
    const float* Ag = hidden + (size_t)(m0 + lr) * H_ + lc;
    const float* Bg = W      + (size_t)(n0 + lr) * H_ + lc;

    for (int k0 = 0; k0 < H_; k0 += 32) {
        __syncthreads();
#pragma unroll
        for (int i = 0; i < 4; i++) {
            float4 va = *(const float4*)(Ag + (size_t)i * 32 * H_ + k0);
            uint32_t* pa = &As[(lr + i * 32) * QPAD + lc];
            pa[0] = f2tf(va.x); pa[1] = f2tf(va.y); pa[2] = f2tf(va.z); pa[3] = f2tf(va.w);
            float4 vb = *(const float4*)(Bg + (size_t)i * 32 * H_ + k0);
            uint32_t* pb = &Bs[(lr + i * 32) * QPAD + lc];
            pb[0] = f2tf(vb.x); pb[1] = f2tf(vb.y); pb[2] = f2tf(vb.z); pb[3] = f2tf(vb.w);
        }
        __syncthreads();
#pragma unroll
        for (int kk = 0; kk < 4; kk++) {
            uint32_t a[4][4], bf[4][2];
            const int c = kk * 8 + tig;
#pragma unroll
            for (int mi = 0; mi < 4; mi++) {
                int r = wm + mi * 16 + gid;
                a[mi][0] = As[r * QPAD + c];
                a[mi][1] = As[(r + 8) * QPAD + c];
                a[mi][2] = As[r * QPAD + c + 4];
                a[mi][3] = As[(r + 8) * QPAD + c + 4];
            }
#pragma unroll
            for (int ni = 0; ni < 4; ni++) {
                int rn = wn + ni * 8 + gid;
                bf[ni][0] = Bs[rn * QPAD + c];
                bf[ni][1] = Bs[rn * QPAD + c + 4];
            }
#pragma unroll
            for (int mi = 0; mi < 4; mi++)
#pragma unroll
                for (int ni = 0; ni < 4; ni++)
                    mma8(acc[mi][ni], a[mi], bf[ni]);
        }
    }

    // epilogue: bias + store into [B, nh, S, hd]
#pragma unroll
    for (int ni = 0; ni < 4; ni++) {
        int gn = n0 + wn + ni * 8 + 2 * tig;
        float b0 = __ldg(bias + gn), b1 = __ldg(bias + gn + 1);
        int hh = gn >> 6, dd = gn & 63;
#pragma unroll
        for (int mi = 0; mi < 4; mi++) {
            int gm = m0 + wm + mi * 16 + gid;
            int bb = gm >> 6, ss = gm & 63;
            float2 v0 = { acc[mi][ni][0] + b0, acc[mi][ni][1] + b1 };
            *(float2*)(dst + (((size_t)bb * NH_ + hh) * S_ + ss) * HD_ + dd) = v0;
            int gm2 = gm + 8;
            bb = gm2 >> 6; ss = gm2 & 63;
            float2 v1 = { acc[mi][ni][2] + b0, acc[mi][ni][3] + b1 };
            *(float2*)(dst + (((size_t)bb * NH_ + hh) * S_ + ss) * HD_ + dd) = v1;
        }
    }
}

// ===========================================================================
// Kernel 2: attention via tf32 mma.sync + online softmax.
// One block per (b,h), 4 warps x 16 q-rows. 32-key K/V tiles in smem.
// P stays in registers: C-fragment -> A-fragment via quad shuffles.
// ===========================================================================
#define KPAD 72   // 64 + 8: stride ≡ 8 (mod 32) → conflict-free frag LDS

__global__ __launch_bounds__(128) void attn_mma_kernel(
    const float* __restrict__ kout, const float* __restrict__ vout,
    const float* __restrict__ c0k,  const float* __restrict__ c0v,
    const float* __restrict__ c1k,  const float* __restrict__ c1v,
    const float* __restrict__ mask, float* __restrict__ out)
{
    __shared__ uint32_t qs[64 * KPAD];
    __shared__ uint32_t ks[32 * KPAD];
    __shared__ uint32_t vs[32 * KPAD];
    __shared__ float msm[32];

    const unsigned FULL = 0xffffffffu;
    const int bh = blockIdx.x, b = bh / NH_, h = bh % NH_;
    const int tid = threadIdx.x, lane = tid & 31, warp = tid >> 5;
    const int gid = lane >> 2, tig = lane & 3;

    // stage Q (pre-scaled by 1/sqrt(64)) as tf32
    {
        const float* qp = g_q + (size_t)bh * S_ * HD_;
#pragma unroll
        for (int i = 0; i < 8; i++) {
            int idx = i * 128 + tid;
            int r = idx >> 4, c = (idx & 15) * 4;
            float4 v = *(const float4*)(qp + r * HD_ + c);
            uint32_t* p = &qs[r * KPAD + c];
            p[0] = f2tf(v.x * 0.125f); p[1] = f2tf(v.y * 0.125f);
            p[2] = f2tf(v.z * 0.125f); p[3] = f2tf(v.w * 0.125f);
        }
    }
    __syncthreads();

    uint32_t qf[8][4];
    {
        const int r = warp * 16 + gid;
#pragma unroll
        for (int kk = 0; kk < 8; kk++) {
            int c = kk * 8 + tig;
            qf[kk][0] = qs[r * KPAD + c];
            qf[kk][1] = qs[(r + 8) * KPAD + c];
            qf[kk][2] = qs[r * KPAD + c + 4];
            qf[kk][3] = qs[(r + 8) * KPAD + c + 4];
        }
    }

    float o[8][4];
#pragma unroll
    for (int nd = 0; nd < 8; nd++)
#pragma unroll
        for (int j = 0; j < 4; j++) o[nd][j] = 0.f;
    float m0 = -1e30f, m1 = -1e30f, l0 = 0.f, l1 = 0.f;

    const float* maskb = mask + (size_t)b * LT_;

    for (int seg = 0; seg < 3; seg++) {
        const float *kb, *vb;
        int len, posbase;
        if (seg == 0) {
            size_t off = ((size_t)(b % BS_) * NH_ + h) * L0_ * HD_;
            kb = c0k + off; vb = c0v + off; len = L0_; posbase = 0;
        } else if (seg == 1) {
            size_t off = ((size_t)b * NH_ + h) * L1_ * HD_;
            kb = c1k + off; vb = c1v + off; len = L1_; posbase = L0_;
        } else {
            size_t off = ((size_t)b * NH_ + h) * S_ * HD_;
            kb = kout + off; vb = vout + off; len = S_; posbase = L0_ + L1_;
        }

        for (int t = 0; t < len; t += 32) {
            __syncthreads();
#pragma unroll
            for (int i = 0; i < 4; i++) {
                int idx = i * 128 + tid;
                int r = idx >> 4, c = (idx & 15) * 4;
                float4 kv = *(const float4*)(kb + (size_t)(t + r) * HD_ + c);
                uint32_t* pk = &ks[r * KPAD + c];
                pk[0] = f2tf(kv.x); pk[1] = f2tf(kv.y); pk[2] = f2tf(kv.z); pk[3] = f2tf(kv.w);
                float4 vv = *(const float4*)(vb + (size_t)(t + r) * HD_ + c);
                uint32_t* pv = &vs[r * KPAD + c];
                pv[0] = f2tf(vv.x); pv[1] = f2tf(vv.y); pv[2] = f2tf(vv.z); pv[3] = f2tf(vv.w);
            }
            if (tid < 32) msm[tid] = maskb[posbase + t + tid];
            __syncthreads();

            // scores: S[16 rows][32 keys] per warp
            float sc[4][4];
#pragma unroll
            for (int nb = 0; nb < 4; nb++) {
                sc[nb][0] = sc[nb][1] = sc[nb][2] = sc[nb][3] = 0.f;
#pragma unroll
                for (int kk = 0; kk < 8; kk++) {
                    uint32_t bf[2];
                    int rn = nb * 8 + gid, c = kk * 8 + tig;
                    bf[0] = ks[rn * KPAD + c];
                    bf[1] = ks[rn * KPAD + c + 4];
                    mma8(sc[nb], qf[kk], bf);
                }
                float mk0 = msm[nb * 8 + 2 * tig], mk1 = msm[nb * 8 + 2 * tig + 1];
                sc[nb][0] += mk0; sc[nb][1] += mk1;
                sc[nb][2] += mk0; sc[nb][3] += mk1;
            }

            // online softmax (rows r = gid and r+8)
            float tm0 = -1e30f, tm1 = -1e30f;
#pragma unroll
            for (int nb = 0; nb < 4; nb++) {
                tm0 = fmaxf(tm0, fmaxf(sc[nb][0], sc[nb][1]));
                tm1 = fmaxf(tm1, fmaxf(sc[nb][2], sc[nb][3]));
            }
            tm0 = fmaxf(tm0, __shfl_xor_sync(FULL, tm0, 1));
            tm0 = fmaxf(tm0, __shfl_xor_sync(FULL, tm0, 2));
            tm1 = fmaxf(tm1, __shfl_xor_sync(FULL, tm1, 1));
            tm1 = fmaxf(tm1, __shfl_xor_sync(FULL, tm1, 2));
            float nm0 = fmaxf(m0, tm0), nm1 = fmaxf(m1, tm1);
            float cr0 = __expf(m0 - nm0), cr1 = __expf(m1 - nm1);
            m0 = nm0; m1 = nm1;
            l0 *= cr0; l1 *= cr1;

            uint32_t pt[4][4];
#pragma unroll
            for (int nb = 0; nb < 4; nb++) {
                float p0 = __expf(sc[nb][0] - m0), p1 = __expf(sc[nb][1] - m0);
                float p2 = __expf(sc[nb][2] - m1), p3 = __expf(sc[nb][3] - m1);
                l0 += p0 + p1; l1 += p2 + p3;
                pt[nb][0] = f2tf(p0); pt[nb][1] = f2tf(p1);
                pt[nb][2] = f2tf(p2); pt[nb][3] = f2tf(p3);
            }
#pragma unroll
            for (int nd = 0; nd < 8; nd++) {
                o[nd][0] *= cr0; o[nd][1] *= cr0;
                o[nd][2] *= cr1; o[nd][3] *= cr1;
            }

            // P (C-layout) -> A-fragments via quad shuffles, then P @ V
            const int srcA = (lane & ~3) | (tig >> 1);
            const int srcB = srcA + 2;
            const bool pk = tig & 1;
#pragma unroll
            for (int kc = 0; kc < 4; kc++) {
                uint32_t t0 = __shfl_sync(FULL, pt[kc][0], srcA);
                uint32_t t1 = __shfl_sync(FULL, pt[kc][1], srcA);
                uint32_t t2 = __shfl_sync(FULL, pt[kc][2], srcA);
                uint32_t t3 = __shfl_sync(FULL, pt[kc][3], srcA);
                uint32_t u0 = __shfl_sync(FULL, pt[kc][0], srcB);
                uint32_t u1 = __shfl_sync(FULL, pt[kc][1], srcB);
                uint32_t u2 = __shfl_sync(FULL, pt[kc][2], srcB);
                uint32_t u3 = __shfl_sync(FULL, pt[kc][3], srcB);
                uint32_t pa[4] = { pk ? t1 : t0, pk ? t3 : t2,
                                   pk ? u1 : u0, pk ? u3 : u2 };
#pragma unroll
                for (int nd = 0; nd < 8; nd++) {
                    uint32_t vf[2];
                    int rk = kc * 8 + tig, cn = nd * 8 + gid;
                    vf[0] = vs[rk * KPAD + cn];
                    vf[1] = vs[(rk + 4) * KPAD + cn];
                    mma8(o[nd], pa, vf);
                }
            }
        }
    }

    l0 += __shfl_xor_sync(FULL, l0, 1);
    l0 += __shfl_xor_sync(FULL, l0, 2);
    l1 += __shfl_xor_sync(FULL, l1, 1);
    l1 += __shfl_xor_sync(FULL, l1, 2);
    float i0 = 1.f / l0, i1 = 1.f / l1;

    const int s = warp * 16 + gid;
    float* ob  = out + ((size_t)b * S_ + s) * H_ + h * HD_;
    float* ob2 = out + ((size_t)b * S_ + s + 8) * H_ + h * HD_;
#pragma unroll
    for (int nd = 0; nd < 8; nd++) {
        int d = nd * 8 + 2 * tig;
        float2 v0 = { o[nd][0] * i0, o[nd][1] * i0 };
        float2 v1 = { o[nd][2] * i1, o[nd][3] * i1 };
        *(float2*)(ob + d)  = v0;
        *(float2*)(ob2 + d) = v1;
    }
}

// ---------------------------------------------------------------------------
extern "C" void kernel_launch(void* const* d_in, const int* in_sizes, int n_in,
                              void* d_out, int out_size)
{
    const float* hidden = (const float*)d_in[0];
    const float* mask   = (const float*)d_in[1];
    const float* Wq     = (const float*)d_in[2];
    const float* bq     = (const float*)d_in[3];
    const float* Wk     = (const float*)d_in[4];
    const float* bk     = (const float*)d_in[5];
    const float* Wv     = (const float*)d_in[6];
    const float* bv     = (const float*)d_in[7];
    const float* c0k    = (const float*)d_in[8];
    const float* c0v    = (const float*)d_in[9];
    const float* c1k    = (const float*)d_in[10];
    const float* c1v    = (const float*)d_in[11];

    float* out  = (float*)d_out;
    float* kout = out + (size_t)OUTSZ;
    float* vout = out + (size_t)2 * OUTSZ;

    dim3 g1(6, 120, 3);
    qkv_mma_kernel<<<g1, 256>>>(hidden, Wq, bq, Wk, bk, Wv, bv, kout, vout);

    attn_mma_kernel<<<B_ * NH_, 128>>>(kout, vout, c0k, c0v, c1k, c1v, mask, out);
}